// round 1
// baseline (speedup 1.0000x reference)
#include <cuda_runtime.h>
#include <cuda_bf16.h>
#include <math.h>

// Problem constants (fixed by the dataset)
#define N0   300000
#define N1   60000
#define N2   6000
#define E1C  1200000
#define E2C  300000
#define RR   4
#define DIN  128
#define DH   128
#define DOUT 64
#define HBUFN 30000
#define NKEYS (N2*RR)          // 24000 (d,r) segments
#define BN_EPS 1e-5f

// ---------------- scratch (static device globals; no runtime allocation) ----
static __device__ __align__(16) float g_h[(size_t)N1 * DH];   // layer-1 output (post history overwrite)
static __device__ int   g_q[E1C];          // layer-1 edges whose dst is "needy"
static __device__ int   g_qcount;
static __device__ int   g_needy[N1];       // rows with history_map < 0
static __device__ int   g_ncount;
static __device__ float g_bnsum[DH];
static __device__ float g_bnsq[DH];
static __device__ float g_scale[DH];
static __device__ float g_shift[DH];
static __device__ int   g_counts[NKEYS + 1];
static __device__ int   g_offsets[NKEYS + 1];
static __device__ int   g_cursor[NKEYS];
static __device__ int   g_esrc[E2C];       // edge srcs sorted by (dst,rel)

// ---------------- K0: zero per-replay state -------------------------------
__global__ void k0_zero() {
    int i = blockIdx.x * blockDim.x + threadIdx.x;
    int stride = gridDim.x * blockDim.x;
    for (int idx = i; idx <= NKEYS; idx += stride) g_counts[idx] = 0;
    if (i < DH) { g_bnsum[i] = 0.f; g_bnsq[i] = 0.f; }
    if (i == 0) { g_qcount = 0; g_ncount = 0; }
}

// ---------------- K1: h = history gather; detect needy rows ---------------
__global__ void k1_gather(const int* __restrict__ hmap,
                          const float4* __restrict__ hist4) {
    const int total = N1 * (DH / 4);              // float4 elements
    for (int i = blockIdx.x * blockDim.x + threadIdx.x; i < total;
         i += gridDim.x * blockDim.x) {
        int d = i >> 5;          // DH/4 = 32 float4 per row
        int q = i & 31;
        int m = __ldg(hmap + d);
        if (m >= 0) {
            reinterpret_cast<float4*>(g_h)[i] = hist4[m * 32 + q];
        } else if (q == 0) {
            int p = atomicAdd(&g_ncount, 1);
            g_needy[p] = d;
        }
    }
}

// ---------------- K1b: needy rows get self-loop + bias --------------------
__global__ void k1b_self(const float* __restrict__ x,
                         const float* __restrict__ Wself1,
                         const float* __restrict__ b1) {
    __shared__ float xs[DIN];
    int t = threadIdx.x;                         // 128 threads, t = output col
    for (int j = blockIdx.x; j < g_ncount; j += gridDim.x) {
        int d = g_needy[j];
        xs[t] = x[(size_t)d * DIN + t];
        __syncthreads();
        float acc = b1[t];
        #pragma unroll 8
        for (int i = 0; i < DIN; i++) acc = fmaf(xs[i], Wself1[i * DH + t], acc);
        g_h[(size_t)d * DH + t] = acc;
        __syncthreads();
    }
}

// ---------------- K2a: scan layer-1 edges for needy dsts ------------------
__global__ void k2a_scan(const int* __restrict__ dst1,
                         const int* __restrict__ hmap, int e1n) {
    for (int e = blockIdx.x * blockDim.x + threadIdx.x; e < e1n;
         e += gridDim.x * blockDim.x) {
        if (__ldg(hmap + __ldg(dst1 + e)) < 0) {
            int p = atomicAdd(&g_qcount, 1);
            g_q[p] = e;
        }
    }
}

// ---------------- K2b: message for each needy edge, add into h ------------
__global__ void k2b_msg(const float* __restrict__ x,
                        const int* __restrict__ src1,
                        const int* __restrict__ dst1,
                        const int* __restrict__ et1,
                        const float* __restrict__ W1) {
    __shared__ float xs[DIN];
    int t = threadIdx.x;                         // 128 threads
    for (int j = blockIdx.x; j < g_qcount; j += gridDim.x) {
        int e = g_q[j];
        int s = src1[e], d = dst1[e], r = et1[e];
        xs[t] = x[(size_t)s * DIN + t];
        __syncthreads();
        float acc = 0.f;
        const float* w = W1 + (size_t)r * DIN * DH + t;
        #pragma unroll 8
        for (int i = 0; i < DIN; i++) acc = fmaf(xs[i], w[i * DH], acc);
        atomicAdd(&g_h[(size_t)d * DH + t], acc);
        __syncthreads();
    }
}

// ---------------- K3: batchnorm statistics (sum / sumsq per column) -------
__global__ void k3_bnstats() {
    int t = threadIdx.x;                         // 128 threads = columns
    float s = 0.f, ss = 0.f;
    for (int row = blockIdx.x; row < N1; row += gridDim.x) {
        float v = g_h[(size_t)row * DH + t];
        s += v;
        ss = fmaf(v, v, ss);
    }
    atomicAdd(&g_bnsum[t], s);
    atomicAdd(&g_bnsq[t], ss);
}

// ---------------- K4: BN scale/shift --------------------------------------
__global__ void k4_bnparams(const float* __restrict__ gamma,
                            const float* __restrict__ beta) {
    int t = threadIdx.x;
    float mean = g_bnsum[t] * (1.0f / N1);
    float var  = g_bnsq[t] * (1.0f / N1) - mean * mean;
    float sc   = gamma[t] * rsqrtf(var + BN_EPS);
    g_scale[t] = sc;
    g_shift[t] = beta[t] - mean * sc;
}

// ---------------- C2: histogram of (dst,rel) keys for layer 2 -------------
__global__ void c2_hist(const int* __restrict__ dst2,
                        const int* __restrict__ et2, int e2n) {
    for (int e = blockIdx.x * blockDim.x + threadIdx.x; e < e2n;
         e += gridDim.x * blockDim.x) {
        int key = __ldg(dst2 + e) * RR + __ldg(et2 + e);
        atomicAdd(&g_counts[key], 1);
    }
}

// ---------------- C3: single-block exclusive scan over 24000 keys ---------
__global__ void c3_scan() {
    __shared__ int part[1024];
    int t = threadIdx.x;
    const int CH = (NKEYS + 1023) / 1024;        // 24
    int beg = t * CH;
    int end = min(beg + CH, NKEYS);
    int s = 0;
    for (int i = beg; i < end; i++) s += g_counts[i];
    part[t] = s;
    __syncthreads();
    for (int off = 1; off < 1024; off <<= 1) {
        int v = (t >= off) ? part[t - off] : 0;
        __syncthreads();
        part[t] += v;
        __syncthreads();
    }
    int run = part[t] - s;                        // exclusive prefix
    for (int i = beg; i < end; i++) {
        g_offsets[i] = run;
        g_cursor[i]  = run;
        run += g_counts[i];
    }
    if (t == 1023) g_offsets[NKEYS] = part[1023];
}

// ---------------- C4: scatter edge srcs into segment order ----------------
__global__ void c4_scatter(const int* __restrict__ src2,
                           const int* __restrict__ dst2,
                           const int* __restrict__ et2, int e2n) {
    for (int e = blockIdx.x * blockDim.x + threadIdx.x; e < e2n;
         e += gridDim.x * blockDim.x) {
        int key = __ldg(dst2 + e) * RR + __ldg(et2 + e);
        int p = atomicAdd(&g_cursor[key], 1);
        g_esrc[p] = __ldg(src2 + e);
    }
}

// ---------------- K5: fused layer-2: aggregate + GEMV + self + log-softmax
__global__ void k5_out(const float* __restrict__ W2,
                       const float* __restrict__ Wself2,
                       const float* __restrict__ b2,
                       float* __restrict__ out) {
    __shared__ float A[RR][DH];
    __shared__ float S[DH];
    __shared__ float O[DOUT];
    __shared__ float red[2];
    int d = blockIdx.x;                          // one block per dst row
    int t = threadIdx.x;                         // 128 threads = feature col
    float sc = g_scale[t], sh = g_shift[t];

    // aggregate incoming messages per relation (BN+ReLU applied on the fly)
    #pragma unroll
    for (int r = 0; r < RR; r++) {
        int beg = g_offsets[d * RR + r];
        int end = g_offsets[d * RR + r + 1];
        float acc = 0.f;
        int j = beg;
        for (; j + 4 <= end; j += 4) {
            int s0 = g_esrc[j], s1 = g_esrc[j + 1];
            int s2 = g_esrc[j + 2], s3 = g_esrc[j + 3];
            float v0 = g_h[(size_t)s0 * DH + t];
            float v1 = g_h[(size_t)s1 * DH + t];
            float v2 = g_h[(size_t)s2 * DH + t];
            float v3 = g_h[(size_t)s3 * DH + t];
            acc += fmaxf(fmaf(sc, v0, sh), 0.f);
            acc += fmaxf(fmaf(sc, v1, sh), 0.f);
            acc += fmaxf(fmaf(sc, v2, sh), 0.f);
            acc += fmaxf(fmaf(sc, v3, sh), 0.f);
        }
        for (; j < end; j++) {
            float v = g_h[(size_t)g_esrc[j] * DH + t];
            acc += fmaxf(fmaf(sc, v, sh), 0.f);
        }
        A[r][t] = acc;
    }
    // self-loop input (d < N2 <= N1)
    S[t] = fmaxf(fmaf(sc, g_h[(size_t)d * DH + t], sh), 0.f);
    __syncthreads();

    // out[d, o] = b2 + S . Wself2[:,o] + sum_r A[r] . W2[r,:,o]
    if (t < DOUT) {
        float val = b2[t];
        #pragma unroll 4
        for (int i = 0; i < DH; i++) val = fmaf(S[i], Wself2[i * DOUT + t], val);
        #pragma unroll
        for (int r = 0; r < RR; r++) {
            const float* w = W2 + (size_t)r * DH * DOUT + t;
            #pragma unroll 4
            for (int i = 0; i < DH; i++) val = fmaf(A[r][i], w[i * DOUT], val);
        }
        O[t] = val;
    }
    __syncthreads();

    // log-softmax over 64 outputs
    if (t < 32) {
        float m = fmaxf(O[t], O[t + 32]);
        #pragma unroll
        for (int off = 16; off; off >>= 1)
            m = fmaxf(m, __shfl_xor_sync(0xffffffffu, m, off));
        float e = expf(O[t] - m) + expf(O[t + 32] - m);
        #pragma unroll
        for (int off = 16; off; off >>= 1)
            e += __shfl_xor_sync(0xffffffffu, e, off);
        if (t == 0) { red[0] = m; red[1] = logf(e); }
    }
    __syncthreads();
    if (t < DOUT) out[(size_t)d * DOUT + t] = O[t] - red[0] - red[1];
}

// ---------------- launch ---------------------------------------------------
extern "C" void kernel_launch(void* const* d_in, const int* in_sizes, int n_in,
                              void* d_out, int out_size) {
    const float* x      = (const float*)d_in[0];
    const int*   src1   = (const int*)d_in[1];
    const int*   dst1   = (const int*)d_in[2];
    const int*   et1    = (const int*)d_in[3];
    const int*   src2   = (const int*)d_in[4];
    const int*   dst2   = (const int*)d_in[5];
    const int*   et2    = (const int*)d_in[6];
    const int*   hmap   = (const int*)d_in[7];
    const float* hist   = (const float*)d_in[8];
    const float* W1     = (const float*)d_in[9];
    const float* Wself1 = (const float*)d_in[10];
    const float* b1     = (const float*)d_in[11];
    const float* gamma  = (const float*)d_in[12];
    const float* beta   = (const float*)d_in[13];
    const float* W2     = (const float*)d_in[14];
    const float* Wself2 = (const float*)d_in[15];
    const float* b2     = (const float*)d_in[16];
    float* out = (float*)d_out;

    int e1n = in_sizes[1];
    int e2n = in_sizes[4];

    k0_zero<<<96, 256>>>();
    k1_gather<<<2048, 256>>>(hmap, (const float4*)hist);
    k1b_self<<<64, 128>>>(x, Wself1, b1);
    k2a_scan<<<1024, 256>>>(dst1, hmap, e1n);
    k2b_msg<<<128, 128>>>(x, src1, dst1, et1, W1);
    k3_bnstats<<<512, 128>>>();
    k4_bnparams<<<1, 128>>>(gamma, beta);
    c2_hist<<<1024, 256>>>(dst2, et2, e2n);
    c3_scan<<<1, 1024>>>();
    c4_scatter<<<1024, 256>>>(src2, dst2, et2, e2n);
    k5_out<<<N2, 128>>>(W2, Wself2, b2, out);
}

// round 2
// speedup vs baseline: 1.4638x; 1.4638x over previous
#include <cuda_runtime.h>
#include <cuda_bf16.h>
#include <math.h>

// Problem constants (fixed by the dataset)
#define N0   300000
#define N1   60000
#define N2   6000
#define E1C  1200000
#define E2C  300000
#define RR   4
#define DIN  128
#define DH   128
#define DOUT 64
#define HBUFN 30000
#define NKEYS (N2*RR)          // 24000 (d,r) segments
#define KTOT  (RR*DH + DH)     // 640 concat K for layer-2 GEMM
#define BN_EPS 1e-5f

// ---------------- scratch (static device globals; no runtime allocation) ----
static __device__ __align__(16) float g_h[(size_t)N1 * DH];   // layer-1 output
static __device__ __align__(16) float g_A[(size_t)N2 * KTOT]; // layer-2 aggregates
static __device__ int   g_q[E1C];          // layer-1 edges whose dst is "needy"
static __device__ int   g_qcount;
static __device__ int   g_needy[N1];       // rows with history_map < 0
static __device__ int   g_ncount;
static __device__ float g_bnsum[DH];
static __device__ float g_bnsq[DH];
static __device__ float g_scale[DH];
static __device__ float g_shift[DH];
static __device__ int   g_counts[NKEYS + 1];
static __device__ int   g_offsets[NKEYS + 1];
static __device__ int   g_cursor[NKEYS];
static __device__ int   g_esrc[E2C];       // edge srcs sorted by (dst,rel)

// ---------------- K0: zero per-replay state -------------------------------
__global__ void k0_zero() {
    int i = blockIdx.x * blockDim.x + threadIdx.x;
    int stride = gridDim.x * blockDim.x;
    for (int idx = i; idx <= NKEYS; idx += stride) g_counts[idx] = 0;
    if (i < DH) { g_bnsum[i] = 0.f; g_bnsq[i] = 0.f; }
    if (i == 0) { g_qcount = 0; g_ncount = 0; }
}

// ---------------- K1: h = history gather + BN partial stats + needy list --
__global__ void __launch_bounds__(256) k1_gather(const int* __restrict__ hmap,
                                                 const float4* __restrict__ hist4) {
    float s0=0.f,s1=0.f,s2=0.f,s3=0.f, q0=0.f,q1=0.f,q2=0.f,q3=0.f;
    const int total = N1 * 32;                 // float4 elements
    int stride = gridDim.x * blockDim.x;       // multiple of 32
    for (int i = blockIdx.x * blockDim.x + threadIdx.x; i < total; i += stride) {
        int d = i >> 5;
        int qq = i & 31;
        int m = __ldg(hmap + d);
        if (m >= 0) {
            float4 v = hist4[m * 32 + qq];
            reinterpret_cast<float4*>(g_h)[i] = v;
            s0 += v.x; q0 = fmaf(v.x, v.x, q0);
            s1 += v.y; q1 = fmaf(v.y, v.y, q1);
            s2 += v.z; q2 = fmaf(v.z, v.z, q2);
            s3 += v.w; q3 = fmaf(v.w, v.w, q3);
        } else if (qq == 0) {
            int p = atomicAdd(&g_ncount, 1);
            g_needy[p] = d;
        }
    }
    __shared__ float red[256][4];
    int t = threadIdx.x;
    red[t][0]=s0; red[t][1]=s1; red[t][2]=s2; red[t][3]=s3;
    __syncthreads();
    if (t < 32) {
        float a0=0.f,a1=0.f,a2=0.f,a3=0.f;
        #pragma unroll
        for (int w = 0; w < 8; w++) {
            a0 += red[t+32*w][0]; a1 += red[t+32*w][1];
            a2 += red[t+32*w][2]; a3 += red[t+32*w][3];
        }
        atomicAdd(&g_bnsum[t*4+0], a0); atomicAdd(&g_bnsum[t*4+1], a1);
        atomicAdd(&g_bnsum[t*4+2], a2); atomicAdd(&g_bnsum[t*4+3], a3);
    }
    __syncthreads();
    red[t][0]=q0; red[t][1]=q1; red[t][2]=q2; red[t][3]=q3;
    __syncthreads();
    if (t < 32) {
        float a0=0.f,a1=0.f,a2=0.f,a3=0.f;
        #pragma unroll
        for (int w = 0; w < 8; w++) {
            a0 += red[t+32*w][0]; a1 += red[t+32*w][1];
            a2 += red[t+32*w][2]; a3 += red[t+32*w][3];
        }
        atomicAdd(&g_bnsq[t*4+0], a0); atomicAdd(&g_bnsq[t*4+1], a1);
        atomicAdd(&g_bnsq[t*4+2], a2); atomicAdd(&g_bnsq[t*4+3], a3);
    }
}

// ---------------- K1b: needy rows get self-loop + bias --------------------
__global__ void k1b_self(const float* __restrict__ x,
                         const float* __restrict__ Wself1,
                         const float* __restrict__ b1) {
    __shared__ float xs[DIN];
    int t = threadIdx.x;                         // 128 threads, t = output col
    for (int j = blockIdx.x; j < g_ncount; j += gridDim.x) {
        int d = g_needy[j];
        xs[t] = x[(size_t)d * DIN + t];
        __syncthreads();
        float acc = b1[t];
        #pragma unroll 8
        for (int i = 0; i < DIN; i++) acc = fmaf(xs[i], Wself1[i * DH + t], acc);
        g_h[(size_t)d * DH + t] = acc;
        __syncthreads();
    }
}

// ---------------- K2a: scan layer-1 edges for needy dsts + layer-2 hist ---
__global__ void __launch_bounds__(256) k2a_scan(
        const int* __restrict__ dst1, const int* __restrict__ hmap, int e1n,
        const int* __restrict__ dst2, const int* __restrict__ et2, int e2n) {
    int idx = blockIdx.x * blockDim.x + threadIdx.x;
    int stride = gridDim.x * blockDim.x;
    const int4* d14 = (const int4*)dst1;
    int n4 = e1n >> 2;
    for (int i = idx; i < n4; i += stride) {
        int4 dd = __ldg(d14 + i);
        int m0 = __ldg(hmap + dd.x), m1 = __ldg(hmap + dd.y);
        int m2 = __ldg(hmap + dd.z), m3 = __ldg(hmap + dd.w);
        if (m0 < 0) g_q[atomicAdd(&g_qcount, 1)] = 4*i + 0;
        if (m1 < 0) g_q[atomicAdd(&g_qcount, 1)] = 4*i + 1;
        if (m2 < 0) g_q[atomicAdd(&g_qcount, 1)] = 4*i + 2;
        if (m3 < 0) g_q[atomicAdd(&g_qcount, 1)] = 4*i + 3;
    }
    for (int e = (n4 << 2) + idx; e < e1n; e += stride)
        if (__ldg(hmap + __ldg(dst1 + e)) < 0)
            g_q[atomicAdd(&g_qcount, 1)] = e;
    // layer-2 histogram
    const int4* d24 = (const int4*)dst2;
    const int4* t24 = (const int4*)et2;
    int h4 = e2n >> 2;
    for (int i = idx; i < h4; i += stride) {
        int4 dd = __ldg(d24 + i);
        int4 tt = __ldg(t24 + i);
        atomicAdd(&g_counts[dd.x * RR + tt.x], 1);
        atomicAdd(&g_counts[dd.y * RR + tt.y], 1);
        atomicAdd(&g_counts[dd.z * RR + tt.z], 1);
        atomicAdd(&g_counts[dd.w * RR + tt.w], 1);
    }
    for (int e = (h4 << 2) + idx; e < e2n; e += stride)
        atomicAdd(&g_counts[__ldg(dst2 + e) * RR + __ldg(et2 + e)], 1);
}

// ---------------- K2b: message for each needy edge, add into h ------------
__global__ void k2b_msg(const float* __restrict__ x,
                        const int* __restrict__ src1,
                        const int* __restrict__ dst1,
                        const int* __restrict__ et1,
                        const float* __restrict__ W1) {
    __shared__ float xs[DIN];
    int t = threadIdx.x;                         // 128 threads
    for (int j = blockIdx.x; j < g_qcount; j += gridDim.x) {
        int e = g_q[j];
        int s = src1[e], d = dst1[e], r = et1[e];
        xs[t] = x[(size_t)s * DIN + t];
        __syncthreads();
        float acc = 0.f;
        const float* w = W1 + (size_t)r * DIN * DH + t;
        #pragma unroll 8
        for (int i = 0; i < DIN; i++) acc = fmaf(xs[i], w[i * DH], acc);
        atomicAdd(&g_h[(size_t)d * DH + t], acc);
        __syncthreads();
    }
}

// ---------------- K3b: add needy rows' contribution to BN stats -----------
__global__ void k3b_needy() {
    int t = threadIdx.x;                         // 128 threads, 1 block
    float s = 0.f, ss = 0.f;
    int n = g_ncount;
    for (int j = 0; j < n; j++) {
        float v = g_h[(size_t)g_needy[j] * DH + t];
        s += v;
        ss = fmaf(v, v, ss);
    }
    atomicAdd(&g_bnsum[t], s);
    atomicAdd(&g_bnsq[t], ss);
}

// ---------------- C3: BN params + single-block exclusive scan -------------
__global__ void c3_scan_bn(const float* __restrict__ gamma,
                           const float* __restrict__ beta) {
    int t = threadIdx.x;                          // 1024 threads
    if (t < DH) {
        float mean = g_bnsum[t] * (1.0f / N1);
        float var  = g_bnsq[t] * (1.0f / N1) - mean * mean;
        float sc   = gamma[t] * rsqrtf(var + BN_EPS);
        g_scale[t] = sc;
        g_shift[t] = beta[t] - mean * sc;
    }
    __shared__ int part[1024];
    const int CH = (NKEYS + 1023) / 1024;        // 24
    int beg = t * CH;
    int end = min(beg + CH, NKEYS);
    int s = 0;
    for (int i = beg; i < end; i++) s += g_counts[i];
    part[t] = s;
    __syncthreads();
    for (int off = 1; off < 1024; off <<= 1) {
        int v = (t >= off) ? part[t - off] : 0;
        __syncthreads();
        part[t] += v;
        __syncthreads();
    }
    int run = part[t] - s;                        // exclusive prefix
    for (int i = beg; i < end; i++) {
        g_offsets[i] = run;
        g_cursor[i]  = run;
        run += g_counts[i];
    }
    if (t == 1023) g_offsets[NKEYS] = part[1023];
}

// ---------------- C4: scatter edge srcs into segment order ----------------
__global__ void __launch_bounds__(256) c4_scatter(
        const int* __restrict__ src2, const int* __restrict__ dst2,
        const int* __restrict__ et2, int e2n) {
    int idx = blockIdx.x * blockDim.x + threadIdx.x;
    int stride = gridDim.x * blockDim.x;
    const int4* s4 = (const int4*)src2;
    const int4* d4 = (const int4*)dst2;
    const int4* t4 = (const int4*)et2;
    int n4 = e2n >> 2;
    for (int i = idx; i < n4; i += stride) {
        int4 ss = __ldg(s4 + i);
        int4 dd = __ldg(d4 + i);
        int4 tt = __ldg(t4 + i);
        g_esrc[atomicAdd(&g_cursor[dd.x * RR + tt.x], 1)] = ss.x;
        g_esrc[atomicAdd(&g_cursor[dd.y * RR + tt.y], 1)] = ss.y;
        g_esrc[atomicAdd(&g_cursor[dd.z * RR + tt.z], 1)] = ss.z;
        g_esrc[atomicAdd(&g_cursor[dd.w * RR + tt.w], 1)] = ss.w;
    }
    for (int e = (n4 << 2) + idx; e < e2n; e += stride) {
        int key = __ldg(dst2 + e) * RR + __ldg(et2 + e);
        g_esrc[atomicAdd(&g_cursor[key], 1)] = __ldg(src2 + e);
    }
}

// ---------------- K5a: per-dst aggregation (BN+ReLU on the fly) -----------
__global__ void __launch_bounds__(128) k5a_agg() {
    int d = blockIdx.x;                          // one block per dst row
    int t = threadIdx.x;                         // 128 threads = feature col
    float sc = g_scale[t], sh = g_shift[t];
    float* Ad = g_A + (size_t)d * KTOT;
    #pragma unroll
    for (int r = 0; r < RR; r++) {
        int beg = g_offsets[d * RR + r];
        int end = g_offsets[d * RR + r + 1];
        float acc = 0.f;
        int j = beg;
        for (; j + 4 <= end; j += 4) {
            int s0 = g_esrc[j], s1 = g_esrc[j + 1];
            int s2 = g_esrc[j + 2], s3 = g_esrc[j + 3];
            float v0 = g_h[(size_t)s0 * DH + t];
            float v1 = g_h[(size_t)s1 * DH + t];
            float v2 = g_h[(size_t)s2 * DH + t];
            float v3 = g_h[(size_t)s3 * DH + t];
            acc += fmaxf(fmaf(sc, v0, sh), 0.f);
            acc += fmaxf(fmaf(sc, v1, sh), 0.f);
            acc += fmaxf(fmaf(sc, v2, sh), 0.f);
            acc += fmaxf(fmaf(sc, v3, sh), 0.f);
        }
        for (; j < end; j++) {
            float v = g_h[(size_t)g_esrc[j] * DH + t];
            acc += fmaxf(fmaf(sc, v, sh), 0.f);
        }
        Ad[r * DH + t] = acc;
    }
    // self-loop input (d < N2 <= N1)
    Ad[RR * DH + t] = fmaxf(fmaf(sc, g_h[(size_t)d * DH + t], sh), 0.f);
}

// ---------------- K5b: tiled GEMM [6000,640]x[640,64] + bias + log-softmax
#define TMB 32
#define KB  16
#define NCH (KTOT / KB)      // 40

__global__ void __launch_bounds__(128) k5b_gemm(const float* __restrict__ W2,
                                                const float* __restrict__ Wself2,
                                                const float* __restrict__ b2,
                                                float* __restrict__ out) {
    __shared__ float As[KB][TMB + 4];            // stride 36 floats
    __shared__ float Ws[KB][DOUT];
    int tid = threadIdx.x;
    int tc = tid & 15;                           // col group (4 cols)
    int tr = tid >> 4;                           // row group (4 rows), 0..7
    int row0 = blockIdx.x * TMB;

    int m_l = tid >> 2;                          // 0..31
    int k_l = (tid & 3) * 4;                     // 0,4,8,12
    int arow = min(row0 + m_l, N2 - 1);
    const float* Ab = g_A + (size_t)arow * KTOT + k_l;

    int k_w = tid >> 3;                          // 0..15
    int c_w = (tid & 7) * 8;                     // 0..56

    float4 pa, pw0, pw1;
    pa = *(const float4*)Ab;
    {
        const float* wp = W2 + (size_t)k_w * DOUT + c_w;   // chunk 0: k < 512
        pw0 = *(const float4*)wp;
        pw1 = *(const float4*)(wp + 4);
    }

    float acc[4][4];
    #pragma unroll
    for (int m = 0; m < 4; m++)
        #pragma unroll
        for (int c = 0; c < 4; c++) acc[m][c] = 0.f;

    for (int kc = 0; kc < NCH; kc++) {
        __syncthreads();
        As[k_l + 0][m_l] = pa.x;
        As[k_l + 1][m_l] = pa.y;
        As[k_l + 2][m_l] = pa.z;
        As[k_l + 3][m_l] = pa.w;
        *(float4*)&Ws[k_w][c_w]     = pw0;
        *(float4*)&Ws[k_w][c_w + 4] = pw1;
        __syncthreads();
        if (kc + 1 < NCH) {
            pa = *(const float4*)(Ab + (kc + 1) * KB);
            int kk = (kc + 1) * KB + k_w;
            const float* wp = (kk < RR * DH)
                ? W2 + (size_t)kk * DOUT + c_w
                : Wself2 + (size_t)(kk - RR * DH) * DOUT + c_w;
            pw0 = *(const float4*)wp;
            pw1 = *(const float4*)(wp + 4);
        }
        #pragma unroll
        for (int k = 0; k < KB; k++) {
            float4 a = *(float4*)&As[k][tr * 4];
            float4 w = *(float4*)&Ws[k][tc * 4];
            acc[0][0] = fmaf(a.x, w.x, acc[0][0]);
            acc[0][1] = fmaf(a.x, w.y, acc[0][1]);
            acc[0][2] = fmaf(a.x, w.z, acc[0][2]);
            acc[0][3] = fmaf(a.x, w.w, acc[0][3]);
            acc[1][0] = fmaf(a.y, w.x, acc[1][0]);
            acc[1][1] = fmaf(a.y, w.y, acc[1][1]);
            acc[1][2] = fmaf(a.y, w.z, acc[1][2]);
            acc[1][3] = fmaf(a.y, w.w, acc[1][3]);
            acc[2][0] = fmaf(a.z, w.x, acc[2][0]);
            acc[2][1] = fmaf(a.z, w.y, acc[2][1]);
            acc[2][2] = fmaf(a.z, w.z, acc[2][2]);
            acc[2][3] = fmaf(a.z, w.w, acc[2][3]);
            acc[3][0] = fmaf(a.w, w.x, acc[3][0]);
            acc[3][1] = fmaf(a.w, w.y, acc[3][1]);
            acc[3][2] = fmaf(a.w, w.z, acc[3][2]);
            acc[3][3] = fmaf(a.w, w.w, acc[3][3]);
        }
    }

    // epilogue: bias + log-softmax per row (16 lanes share one row)
    float4 bb = *(const float4*)(b2 + tc * 4);
    #pragma unroll
    for (int m = 0; m < 4; m++) {
        int row = row0 + tr * 4 + m;
        float v0 = acc[m][0] + bb.x;
        float v1 = acc[m][1] + bb.y;
        float v2 = acc[m][2] + bb.z;
        float v3 = acc[m][3] + bb.w;
        float mx = fmaxf(fmaxf(v0, v1), fmaxf(v2, v3));
        #pragma unroll
        for (int off = 1; off < 16; off <<= 1)
            mx = fmaxf(mx, __shfl_xor_sync(0xffffffffu, mx, off));
        float es = expf(v0 - mx) + expf(v1 - mx) + expf(v2 - mx) + expf(v3 - mx);
        #pragma unroll
        for (int off = 1; off < 16; off <<= 1)
            es += __shfl_xor_sync(0xffffffffu, es, off);
        float l = mx + logf(es);
        if (row < N2) {
            float4 o = make_float4(v0 - l, v1 - l, v2 - l, v3 - l);
            *(float4*)(out + (size_t)row * DOUT + tc * 4) = o;
        }
    }
}

// ---------------- launch ---------------------------------------------------
extern "C" void kernel_launch(void* const* d_in, const int* in_sizes, int n_in,
                              void* d_out, int out_size) {
    const float* x      = (const float*)d_in[0];
    const int*   src1   = (const int*)d_in[1];
    const int*   dst1   = (const int*)d_in[2];
    const int*   et1    = (const int*)d_in[3];
    const int*   src2   = (const int*)d_in[4];
    const int*   dst2   = (const int*)d_in[5];
    const int*   et2    = (const int*)d_in[6];
    const int*   hmap   = (const int*)d_in[7];
    const float* hist   = (const float*)d_in[8];
    const float* W1     = (const float*)d_in[9];
    const float* Wself1 = (const float*)d_in[10];
    const float* b1     = (const float*)d_in[11];
    const float* gamma  = (const float*)d_in[12];
    const float* beta   = (const float*)d_in[13];
    const float* W2     = (const float*)d_in[14];
    const float* Wself2 = (const float*)d_in[15];
    const float* b2     = (const float*)d_in[16];
    float* out = (float*)d_out;

    int e1n = in_sizes[1];
    int e2n = in_sizes[4];

    k0_zero<<<96, 256>>>();
    k1_gather<<<512, 256>>>(hmap, (const float4*)hist);
    k1b_self<<<64, 128>>>(x, Wself1, b1);
    k2a_scan<<<512, 256>>>(dst1, hmap, e1n, dst2, et2, e2n);
    k2b_msg<<<128, 128>>>(x, src1, dst1, et1, W1);
    k3b_needy<<<1, 128>>>();
    c3_scan_bn<<<1, 1024>>>(gamma, beta);
    c4_scatter<<<512, 256>>>(src2, dst2, et2, e2n);
    k5a_agg<<<N2, 128>>>();
    k5b_gemm<<<(N2 + TMB - 1) / TMB, 128>>>(W2, Wself2, b2, out);
}